// round 6
// baseline (speedup 1.0000x reference)
#include <cuda_runtime.h>

#define BB 4
#define NN 2048
#define EE (NN*(NN-1)/2)        // 2,096,128
#define NPAIR (NN/2)            // 1024
#define NBLKS (NPAIR*BB)        // 4096
#define TPB 256
#define NWARP (TPB/32)

__device__ float g_partial[NBLKS];
__device__ unsigned int g_count = 0;

struct Consts {
    float f, omf;
    float qt00, qt01, qt10, qt11;   // qt[a][x] = lik(x)*pr(a)/ev(a==x)
};

__device__ __forceinline__ float edge_term(int a, float uu, float xv, const Consts& c)
{
    const float p1 = a ? c.omf : c.f;            // P(x_t = 1)
    const bool  x  = uu < p1;
    const float q0 = x ? c.qt01 : c.qt00;        // a = 0
    const float q1 = x ? c.qt11 : c.qt10;        // a = 1
    const float qt = a ? q1 : q0;
    // softplus(-|x|) = log1p(exp(-|x|)) via EX2 + LG2
    const float sp = 0.69314718056f * __log2f(1.0f + __expf(-fabsf(xv)));
    return fmaxf(xv, 0.0f) - xv * qt + sp;
}

// Warp-stride mapping: thread tid handles j = tid + k*TPB. Every LDG on every
// array is a fully-coalesced 128B line (1 L1tex wavefront). Loads batched in
// two half-groups of 12 to bound register pressure while keeping MLP high.
__device__ __forceinline__ float row_sum_coal(const int*   __restrict__ arow,
                                              const float* __restrict__ urow,
                                              const float* __restrict__ qrow,
                                              int len, int tid, const Consts& c)
{
    float s = 0.0f;
    #pragma unroll
    for (int h = 0; h < 2; h++) {
        int   av[4];
        float uv[4], qv[4];
        #pragma unroll
        for (int k = 0; k < 4; k++) {
            const int j  = tid + (h * 4 + k) * TPB;
            const bool in = j < len;
            av[k] = in ? arow[j] : 0;
            uv[k] = in ? urow[j] : 2.0f;   // 2.0 > any p1 -> x=0 (value unused anyway)
            qv[k] = in ? qrow[j] : 0.0f;
        }
        #pragma unroll
        for (int k = 0; k < 4; k++) {
            const int j = tid + (h * 4 + k) * TPB;
            if (j < len) s += edge_term(av[k], uv[k], qv[k], c);
        }
    }
    return s;
}

__global__ __launch_bounds__(TPB) void diffusion_fused_kernel(
    const int*   __restrict__ adj,   // [B, N, N] int32
    const int*   __restrict__ t,     // [B]
    const float* __restrict__ u,     // [B, N, N]
    const float* __restrict__ q,     // [B, E]
    float* __restrict__ out)
{
    const int p   = blockIdx.x;      // pair: rows p and NN-1-p (2047 elems total)
    const int b   = blockIdx.y;
    const int tid = threadIdx.x;

    // Per-batch flip probabilities: f = 0.5*(1 - 0.98^(t+1)); t-1 wraps to 999.
    const int tb = t[b];
    const double L2_098 = -0.0291463456595169;   // log2(0.98)
    const float pw  = exp2f((float)((double)(tb + 1) * L2_098));
    const int   tp  = (tb == 0) ? 999 : (tb - 1);
    const float pwp = exp2f((float)((double)(tp + 1) * L2_098));

    Consts c;
    c.f   = 0.5f * (1.0f - pw);
    c.omf = 1.0f - c.f;
    const float fp   = 0.5f * (1.0f - pwp);
    const float omfp = 1.0f - fp;
    const float rf   = __fdividef(1.0f, c.f);
    const float romf = __fdividef(1.0f, c.omf);
    // qt[a][x] = lik(x) * pr(a) / ev(a==x);  ev: equal -> omf, diff -> f
    c.qt00 = 0.01f * fp   * romf;
    c.qt01 = 0.99f * fp   * rf;
    c.qt10 = 0.01f * omfp * rf;
    c.qt11 = 0.99f * omfp * romf;

    const int i1 = p;
    const int i2 = NN - 1 - p;
    const size_t bnn = (size_t)b * NN * NN;
    const size_t bee = (size_t)b * EE;

    float s = 0.0f;
    s += row_sum_coal(adj + bnn + (size_t)i1 * NN, u + bnn + (size_t)i1 * NN,
                      q + bee + ((size_t)i1 * (size_t)(i1 - 1)) / 2, i1, tid, c);
    s += row_sum_coal(adj + bnn + (size_t)i2 * NN, u + bnn + (size_t)i2 * NN,
                      q + bee + ((size_t)i2 * (size_t)(i2 - 1)) / 2, i2, tid, c);

    #pragma unroll
    for (int o = 16; o > 0; o >>= 1)
        s += __shfl_xor_sync(0xFFFFFFFFu, s, o);

    __shared__ float wsum[NWARP];
    __shared__ bool  isLast;
    const int wid = tid >> 5, lid = tid & 31;
    if (lid == 0) wsum[wid] = s;
    __syncthreads();

    if (tid == 0) {
        float bs = 0.0f;
        #pragma unroll
        for (int w = 0; w < NWARP; w++) bs += wsum[w];
        g_partial[blockIdx.y * gridDim.x + blockIdx.x] = bs;
        __threadfence();
        unsigned int old = atomicAdd(&g_count, 1u);
        isLast = (old == (unsigned)(NBLKS - 1));
    }
    __syncthreads();

    if (isLast) {
        __shared__ double dsum[TPB];
        double ds = 0.0;
        for (int idx = tid; idx < NBLKS; idx += TPB)
            ds += (double)g_partial[idx];
        dsum[tid] = ds;
        __syncthreads();
        #pragma unroll
        for (int o = TPB / 2; o > 0; o >>= 1) {
            if (tid < o) dsum[tid] += dsum[tid + o];
            __syncthreads();
        }
        if (tid == 0) {
            out[0] = (float)(dsum[0] / ((double)BB * (double)EE));
            g_count = 0;   // reset for next graph replay
        }
    }
}

extern "C" void kernel_launch(void* const* d_in, const int* in_sizes, int n_in,
                              void* d_out, int out_size)
{
    const int*   adj = (const int*)  d_in[0];
    const int*   t   = (const int*)  d_in[1];
    const float* u   = (const float*)d_in[2];
    const float* q   = (const float*)d_in[3];
    float* out = (float*)d_out;

    dim3 grid(NPAIR, BB);
    diffusion_fused_kernel<<<grid, TPB>>>(adj, t, u, q, out);
}

// round 7
// speedup vs baseline: 1.3380x; 1.3380x over previous
#include <cuda_runtime.h>

#define BB 4
#define NN 2048
#define EE (NN*(NN-1)/2)        // 2,096,128
#define NPAIR (NN/2)            // 1024
#define PAIRS 4                 // pairs per block
#define GX (NPAIR/PAIRS)        // 256
#define NBLKS (GX*BB)           // 1024
#define TPB 256
#define NWARP (TPB/32)

__device__ float g_partial[NBLKS];
__device__ unsigned int g_count = 0;

struct Consts {
    float f, omf;
    float qt00, qt01, qt10, qt11;   // qt[a][x] = lik(x)*pr(a)/ev(a==x)
};

__device__ __forceinline__ float edge_term(int a, float uu, float xv, const Consts& c)
{
    const float p1 = a ? c.omf : c.f;            // P(x_t = 1)
    const bool  x  = uu < p1;
    const float q0 = x ? c.qt01 : c.qt00;        // a = 0
    const float q1 = x ? c.qt11 : c.qt10;        // a = 1
    const float qt = a ? q1 : q0;
    // softplus(-|x|) = log1p(exp(-|x|)) via EX2 + LG2
    const float sp = 0.69314718056f * __log2f(1.0f + __expf(-fabsf(xv)));
    return fmaxf(xv, 0.0f) - xv * qt + sp;
}

// R5 mapping (best measured): thread tid owns elements [8*tid, 8*tid+8).
// 12 loads (2xLDG.128 adj, 2xLDG.128 u, 8xLDG.32 q) issued straight-line,
// consumed into 4 independent accumulators.
__device__ __forceinline__ void row_sum(const int*   __restrict__ arow,
                                        const float* __restrict__ urow,
                                        const float* __restrict__ qrow,
                                        int len, int tid, const Consts& c,
                                        float& s0, float& s1, float& s2, float& s3)
{
    const int g = tid * 8;
    if (g + 8 <= len) {
        const int4   a0 = *reinterpret_cast<const int4*>(arow + g);
        const int4   a1 = *reinterpret_cast<const int4*>(arow + g + 4);
        const float4 u0 = *reinterpret_cast<const float4*>(urow + g);
        const float4 u1 = *reinterpret_cast<const float4*>(urow + g + 4);
        const float  x0 = qrow[g + 0], x1 = qrow[g + 1], x2 = qrow[g + 2], x3 = qrow[g + 3];
        const float  x4 = qrow[g + 4], x5 = qrow[g + 5], x6 = qrow[g + 6], x7 = qrow[g + 7];
        s0 += edge_term(a0.x, u0.x, x0, c);
        s1 += edge_term(a0.y, u0.y, x1, c);
        s2 += edge_term(a0.z, u0.z, x2, c);
        s3 += edge_term(a0.w, u0.w, x3, c);
        s0 += edge_term(a1.x, u1.x, x4, c);
        s1 += edge_term(a1.y, u1.y, x5, c);
        s2 += edge_term(a1.z, u1.z, x6, c);
        s3 += edge_term(a1.w, u1.w, x7, c);
    } else if (g < len) {
        float s = 0.0f;
        for (int j = g; j < len; j++)
            s += edge_term(arow[j], urow[j], qrow[j], c);
        s0 += s;
    }
}

__global__ __launch_bounds__(TPB) void diffusion_fused_kernel(
    const int*   __restrict__ adj,   // [B, N, N] int32
    const int*   __restrict__ t,     // [B]
    const float* __restrict__ u,     // [B, N, N]
    const float* __restrict__ q,     // [B, E]
    float* __restrict__ out)
{
    const int b   = blockIdx.y;
    const int tid = threadIdx.x;

    // Per-batch flip probabilities: f = 0.5*(1 - 0.98^(t+1)); t-1 wraps to 999.
    const int tb = t[b];
    const double L2_098 = -0.0291463456595169;   // log2(0.98)
    const float pw  = exp2f((float)((double)(tb + 1) * L2_098));
    const int   tp  = (tb == 0) ? 999 : (tb - 1);
    const float pwp = exp2f((float)((double)(tp + 1) * L2_098));

    Consts c;
    c.f   = 0.5f * (1.0f - pw);
    c.omf = 1.0f - c.f;
    const float fp   = 0.5f * (1.0f - pwp);
    const float omfp = 1.0f - fp;
    const float rf   = __fdividef(1.0f, c.f);
    const float romf = __fdividef(1.0f, c.omf);
    // qt[a][x] = lik(x) * pr(a) / ev(a==x);  ev: equal -> omf, diff -> f
    c.qt00 = 0.01f * fp   * romf;
    c.qt01 = 0.99f * fp   * rf;
    c.qt10 = 0.01f * omfp * rf;
    c.qt11 = 0.99f * omfp * romf;

    const size_t bnn = (size_t)b * NN * NN;
    const size_t bee = (size_t)b * EE;
    const int*   adjb = adj + bnn;
    const float* ub   = u + bnn;
    const float* qb   = q + bee;

    float s0 = 0.0f, s1 = 0.0f, s2 = 0.0f, s3 = 0.0f;

    #pragma unroll 1
    for (int m = 0; m < PAIRS; m++) {
        const int p  = blockIdx.x * PAIRS + m;
        const int i1 = p;              // short row
        const int i2 = NN - 1 - p;     // long row (i1 + i2 = 2047)
        row_sum(adjb + (size_t)i1 * NN, ub + (size_t)i1 * NN,
                qb + ((size_t)i1 * (size_t)(i1 - 1)) / 2, i1, tid, c, s0, s1, s2, s3);
        row_sum(adjb + (size_t)i2 * NN, ub + (size_t)i2 * NN,
                qb + ((size_t)i2 * (size_t)(i2 - 1)) / 2, i2, tid, c, s0, s1, s2, s3);
    }

    float s = (s0 + s1) + (s2 + s3);
    #pragma unroll
    for (int o = 16; o > 0; o >>= 1)
        s += __shfl_xor_sync(0xFFFFFFFFu, s, o);

    __shared__ float wsum[NWARP];
    __shared__ bool  isLast;
    const int wid = tid >> 5, lid = tid & 31;
    if (lid == 0) wsum[wid] = s;
    __syncthreads();

    if (tid == 0) {
        float bs = 0.0f;
        #pragma unroll
        for (int w = 0; w < NWARP; w++) bs += wsum[w];
        g_partial[blockIdx.y * gridDim.x + blockIdx.x] = bs;
        __threadfence();
        unsigned int old = atomicAdd(&g_count, 1u);
        isLast = (old == (unsigned)(NBLKS - 1));
    }
    __syncthreads();

    if (isLast) {
        __shared__ double dsum[TPB];
        double ds = 0.0;
        for (int idx = tid; idx < NBLKS; idx += TPB)
            ds += (double)g_partial[idx];
        dsum[tid] = ds;
        __syncthreads();
        #pragma unroll
        for (int o = TPB / 2; o > 0; o >>= 1) {
            if (tid < o) dsum[tid] += dsum[tid + o];
            __syncthreads();
        }
        if (tid == 0) {
            out[0] = (float)(dsum[0] / ((double)BB * (double)EE));
            g_count = 0;   // reset for next graph replay
        }
    }
}

extern "C" void kernel_launch(void* const* d_in, const int* in_sizes, int n_in,
                              void* d_out, int out_size)
{
    const int*   adj = (const int*)  d_in[0];
    const int*   t   = (const int*)  d_in[1];
    const float* u   = (const float*)d_in[2];
    const float* q   = (const float*)d_in[3];
    float* out = (float*)d_out;

    dim3 grid(GX, BB);
    diffusion_fused_kernel<<<grid, TPB>>>(adj, t, u, q, out);
}